// round 6
// baseline (speedup 1.0000x reference)
#include <cuda_runtime.h>
#include <cuda_bf16.h>
#include <math.h>
#include <stdint.h>

// Problem constants
#define G 256
#define N0 256
#define HF 256            // hidden feature dim
#define MAXN (G*N0)       // 65536
#define MAXE (G*2048)     // 524288
#define EPG 2048          // edges per graph (fixed slot count, masked edges have ew=0)

// -------- scratch (device globals; no allocation allowed) --------
__device__ float g_h[MAXN*HF];        // 64 MB : h = x @ W
__device__ float g_agg[MAXN*HF];      // 64 MB : conv output
__device__ float g_x[(MAXN/2)*HF];    // 32 MB : pooled features
__device__ float g_dinv[MAXN];
__device__ float g_score[MAXN];
__device__ float g_spart[8*MAXN];     // per-fc-chunk score partials (deterministic sum)
__device__ int   g_newid[MAXN];
__device__ int   g_perm[MAXN/2];
__device__ int   g_esrc0[MAXE], g_edst0[MAXE];
__device__ float g_eew0[MAXE];
__device__ int   g_esrc1[MAXE], g_edst1[MAXE];
__device__ float g_eew1[MAXE];
__device__ int   g_rs[MAXN];
__device__ int   g_rc[MAXN];
__device__ int2  g_cpack[MAXE];       // CSR packed (src, norm-bits)
__device__ float g_ro[G*512];
__device__ float g_h1[G*256];
__device__ float g_h2[G*128];
// W split buffers (bf16, [256 rows (N)] x [K] K-major), K<=256
__device__ __nv_bfloat16 g_whi[256*256];
__device__ __nv_bfloat16 g_wmid[256*256];
__device__ __nv_bfloat16 g_wlo[256*256];

// ================= helpers =================
__device__ __forceinline__ uint32_t smem_u32(const void* p) {
    uint32_t a;
    asm("{ .reg .u64 t; cvta.to.shared.u64 t, %1; cvt.u32.u64 %0, t; }"
        : "=r"(a) : "l"(p));
    return a;
}
__device__ __forceinline__ void ldsm_x4(uint32_t* r, uint32_t addr) {
    asm volatile("ldmatrix.sync.aligned.m8n8.x4.shared.b16 {%0,%1,%2,%3}, [%4];"
        : "=r"(r[0]), "=r"(r[1]), "=r"(r[2]), "=r"(r[3]) : "r"(addr));
}
__device__ __forceinline__ void ldsm_x2(uint32_t* r, uint32_t addr) {
    asm volatile("ldmatrix.sync.aligned.m8n8.x2.shared.b16 {%0,%1}, [%2];"
        : "=r"(r[0]), "=r"(r[1]) : "r"(addr));
}
__device__ __forceinline__ void mma_bf16(float* d, const uint32_t* a, const uint32_t* b) {
    asm volatile("mma.sync.aligned.m16n8k16.row.col.f32.bf16.bf16.f32 "
        "{%0,%1,%2,%3}, {%4,%5,%6,%7}, {%8,%9}, {%0,%1,%2,%3};"
        : "+f"(d[0]), "+f"(d[1]), "+f"(d[2]), "+f"(d[3])
        : "r"(a[0]), "r"(a[1]), "r"(a[2]), "r"(a[3]), "r"(b[0]), "r"(b[1]));
}

// ================= W split kernel (3-way bf16, K-major output) =================
__global__ void wsplit_kernel(const float* __restrict__ W, int K,
                              __nv_bfloat16* __restrict__ whi,
                              __nv_bfloat16* __restrict__ wmid,
                              __nv_bfloat16* __restrict__ wlo) {
    int idx = blockIdx.x * 256 + threadIdx.x;
    if (idx >= K * 256) return;
    int k = idx >> 8, n = idx & 255;
    float w = W[idx];
    __nv_bfloat16 h = __float2bfloat16_rn(w);
    float r1 = w - __bfloat162float(h);
    __nv_bfloat16 m = __float2bfloat16_rn(r1);
    float r2 = r1 - __bfloat162float(m);
    __nv_bfloat16 l = __float2bfloat16_rn(r2);
    whi[n*K + k] = h; wmid[n*K + k] = m; wlo[n*K + k] = l;
}

// ================= MMA GEMM: C[n,256] = X[n,K] @ W[K,256] =================
// fp32-exact via 3-term bf16 split, 6 product segments. (unchanged from R5)
#define SEGB 6144
#define MMA_SMEM (6*SEGB)

__global__ __launch_bounds__(256, 1) void gemm_mma_kernel(
        const float* __restrict__ X,
        const __nv_bfloat16* __restrict__ Whi,
        const __nv_bfloat16* __restrict__ Wmid,
        const __nv_bfloat16* __restrict__ Wlo,
        float* __restrict__ C, int K) {
    extern __shared__ __align__(16) char smem[];
    char* smA = smem;
    char* smB = smem + 3*SEGB;
    uint32_t sb = smem_u32(smem);
    int tid = threadIdx.x, w = tid >> 5, lane = tid & 31;
    int rowBase = blockIdx.x * 128, colBase = blockIdx.y * 128;
    int warpRow = (w >> 2) * 64, warpCol = (w & 3) * 32;

    float acc[4][4][4];
    #pragma unroll
    for (int i = 0; i < 4; i++)
        #pragma unroll
        for (int j = 0; j < 4; j++)
            #pragma unroll
            for (int d = 0; d < 4; d++) acc[i][j][d] = 0.f;

    int r  = tid >> 1;
    int hf = tid & 1;
    uint32_t stOff = (uint32_t)(r * 48 + hf * 16);

    int bl = lane & 15;
    uint32_t aFragBase = sb + (uint32_t)((warpRow + (lane & 15)) * 48 + (lane >> 4) * 16);
    uint32_t bFragBase = sb + 3*SEGB
                       + (uint32_t)((warpCol + (bl & 7)) * 48 + (bl >> 3) * 16);

    const int NC = K >> 4;
    for (int kb = 0; kb < NC; kb++) {
        {
            const float* Ag = X + (size_t)(rowBase + r) * K + kb * 16 + hf * 8;
            float4 v0 = *(const float4*)Ag;
            float4 v1 = *(const float4*)(Ag + 4);
            float f[8] = {v0.x, v0.y, v0.z, v0.w, v1.x, v1.y, v1.z, v1.w};
            ushort hh[8], mm[8], ll[8];
            #pragma unroll
            for (int j = 0; j < 8; j++) {
                __nv_bfloat16 h = __float2bfloat16_rn(f[j]);
                float r1 = f[j] - __bfloat162float(h);
                __nv_bfloat16 m = __float2bfloat16_rn(r1);
                float r2 = r1 - __bfloat162float(m);
                __nv_bfloat16 l = __float2bfloat16_rn(r2);
                hh[j] = __bfloat16_as_ushort(h);
                mm[j] = __bfloat16_as_ushort(m);
                ll[j] = __bfloat16_as_ushort(l);
            }
            uint4 ph, pm, pl;
            ph.x = hh[0] | ((uint32_t)hh[1] << 16); ph.y = hh[2] | ((uint32_t)hh[3] << 16);
            ph.z = hh[4] | ((uint32_t)hh[5] << 16); ph.w = hh[6] | ((uint32_t)hh[7] << 16);
            pm.x = mm[0] | ((uint32_t)mm[1] << 16); pm.y = mm[2] | ((uint32_t)mm[3] << 16);
            pm.z = mm[4] | ((uint32_t)mm[5] << 16); pm.w = mm[6] | ((uint32_t)mm[7] << 16);
            pl.x = ll[0] | ((uint32_t)ll[1] << 16); pl.y = ll[2] | ((uint32_t)ll[3] << 16);
            pl.z = ll[4] | ((uint32_t)ll[5] << 16); pl.w = ll[6] | ((uint32_t)ll[7] << 16);
            *(uint4*)(smA          + stOff) = ph;
            *(uint4*)(smA + SEGB   + stOff) = pm;
            *(uint4*)(smA + 2*SEGB + stOff) = pl;
        }
        {
            size_t goff = (size_t)(colBase + r) * K + kb * 16 + hf * 8;
            *(uint4*)(smB          + stOff) = *(const uint4*)(Whi  + goff);
            *(uint4*)(smB + SEGB   + stOff) = *(const uint4*)(Wmid + goff);
            *(uint4*)(smB + 2*SEGB + stOff) = *(const uint4*)(Wlo  + goff);
        }
        __syncthreads();

        uint32_t bfr[3][4][2];
        #pragma unroll
        for (int s = 0; s < 3; s++)
            #pragma unroll
            for (int nt = 0; nt < 4; nt++)
                ldsm_x2(bfr[s][nt], bFragBase + s*SEGB + nt*(8*48));

        const int ai[6] = {0, 0, 1, 0, 1, 2};
        const int bi[6] = {0, 1, 0, 2, 1, 0};
        #pragma unroll
        for (int mt = 0; mt < 4; mt++) {
            uint32_t afr[3][4];
            #pragma unroll
            for (int s = 0; s < 3; s++)
                ldsm_x4(afr[s], aFragBase + s*SEGB + mt*(16*48));
            #pragma unroll
            for (int cb = 0; cb < 6; cb++)
                #pragma unroll
                for (int nt = 0; nt < 4; nt++)
                    mma_bf16(acc[mt][nt], afr[ai[cb]], bfr[bi[cb]][nt]);
        }
        __syncthreads();
    }

    #pragma unroll
    for (int mt = 0; mt < 4; mt++) {
        int row = rowBase + warpRow + mt*16 + (lane >> 2);
        #pragma unroll
        for (int nt = 0; nt < 4; nt++) {
            int col = colBase + warpCol + nt*8 + (lane & 3)*2;
            *(float2*)&C[(size_t)row * 256 + col] =
                make_float2(acc[mt][nt][0], acc[mt][nt][1]);
            *(float2*)&C[(size_t)(row + 8) * 256 + col] =
                make_float2(acc[mt][nt][2], acc[mt][nt][3]);
        }
    }
}

// ---------------- per-graph CSR build (block = graph, 256 threads) ----------------
__global__ __launch_bounds__(256) void csr_build_kernel(
        const int* __restrict__ src, const int* __restrict__ dst,
        const float* __restrict__ ew, int npg,
        int* __restrict__ rs, int* __restrict__ rc,
        int2* __restrict__ cpack, float* __restrict__ dinv) {
    __shared__ float sdeg[256];
    __shared__ int   scnt[256];
    __shared__ int   sscan[256];
    __shared__ int   spos[256];
    int g = blockIdx.x, t = threadIdx.x;
    int nbase = g * npg, ebase = g * EPG;

    if (t < npg) { sdeg[t] = 1.0f; scnt[t] = 0; }
    __syncthreads();
    for (int e = t; e < EPG; e += 256) {
        float w = ew ? ew[ebase + e] : 1.0f;
        if (w != 0.f) {
            int d = dst[ebase + e] - nbase;
            atomicAdd(&sdeg[d], w);
            atomicAdd(&scnt[d], 1);
        }
    }
    __syncthreads();
    int v = (t < npg) ? scnt[t] : 0;
    sscan[t] = v;
    __syncthreads();
    #pragma unroll
    for (int off = 1; off < 256; off <<= 1) {
        int add = (t >= off) ? sscan[t - off] : 0;
        __syncthreads();
        sscan[t] += add;
        __syncthreads();
    }
    int start = sscan[t] - v;
    if (t < npg) {
        rs[nbase + t] = start;
        rc[nbase + t] = v;
        spos[t] = start;
        dinv[nbase + t] = 1.0f / sdeg[t];
    }
    __syncthreads();
    for (int e = t; e < EPG; e += 256) {
        float w = ew ? ew[ebase + e] : 1.0f;
        if (w != 0.f) {
            int s = src[ebase + e] - nbase;
            int d = dst[ebase + e] - nbase;
            float nm = rsqrtf(sdeg[s]) * rsqrtf(sdeg[d]) * w;
            int idx = atomicAdd(&spos[d], 1);
            cpack[ebase + idx] = make_int2(s, __float_as_int(nm));
        }
    }
}

// ---------------- fused aggregation + self-loop + bias + relu + score partial ----
// block = (fc in [0,8), graph g); stages h tile [npg][32] in smem (32KB max)
__global__ __launch_bounds__(256) void agg_fused_kernel(
        const float* __restrict__ h, const float* __restrict__ dinv,
        const int* __restrict__ rs, const int* __restrict__ rc,
        const int2* __restrict__ cpack, const float* __restrict__ bias,
        const float* __restrict__ pw, float* __restrict__ out,
        float* __restrict__ spart, int npg) {
    extern __shared__ float ht[];   // npg * 32 floats
    int fc = blockIdx.x, g = blockIdx.y;
    int t = threadIdx.x;
    int nbase = g * npg, ebase = g * EPG;

    const float4* h4 = (const float4*)h;
    float4* ht4 = (float4*)ht;
    for (int i = t; i < npg * 8; i += 256) {
        int node = i >> 3, q = i & 7;
        ht4[i] = h4[(size_t)(nbase + node) * 64 + fc * 8 + q];
    }
    __syncthreads();

    int w = t >> 5, lane = t & 31;
    int f = fc * 32 + lane;
    float b   = __ldg(bias + f);
    float pwf = __ldg(pw + f);
    for (int d = w; d < npg; d += 8) {
        float a = ht[d*32 + lane] * dinv[nbase + d] + b;
        int cnt = rc[nbase + d];
        const int2* cp = cpack + ebase + rs[nbase + d];
        int e = 0;
        for (; e + 4 <= cnt; e += 4) {
            int2 p0 = __ldg(cp + e);
            int2 p1 = __ldg(cp + e + 1);
            int2 p2 = __ldg(cp + e + 2);
            int2 p3 = __ldg(cp + e + 3);
            a += __int_as_float(p0.y) * ht[p0.x*32 + lane];
            a += __int_as_float(p1.y) * ht[p1.x*32 + lane];
            a += __int_as_float(p2.y) * ht[p2.x*32 + lane];
            a += __int_as_float(p3.y) * ht[p3.x*32 + lane];
        }
        for (; e < cnt; e++) {
            int2 p = __ldg(cp + e);
            a += __int_as_float(p.y) * ht[p.x*32 + lane];
        }
        float o = fmaxf(a, 0.f);
        out[(size_t)(nbase + d) * 256 + f] = o;
        float sp = o * pwf;
        #pragma unroll
        for (int off = 16; off > 0; off >>= 1)
            sp += __shfl_down_sync(0xFFFFFFFFu, sp, off);
        if (lane == 0) spart[fc * MAXN + nbase + d] = sp;
    }
}

// ---------------- pool: sum partials, tanh, ||w|| inline, rank-count top-k ------
__global__ void pool_kernel(const float* __restrict__ spart,
                            const float* __restrict__ pw,
                            float* __restrict__ score, int npg, int k,
                            int* __restrict__ newid, int* __restrict__ perm) {
    __shared__ float s[256];
    __shared__ float red[256];
    int g = blockIdx.x, t = threadIdx.x;
    // ||w||^2 reduce (redundant per block, trivial)
    float ss = 0.f;
    for (int i = t; i < 256; i += npg) { float v = pw[i]; ss += v * v; }
    red[t] = ss;
    __syncthreads();
    for (int st = npg >> 1; st > 0; st >>= 1) {
        if (t < st) red[t] += red[t + st];
        __syncthreads();
    }
    float winv = rsqrtf(red[0]);

    int node = g * npg + t;
    float acc = 0.f;
    #pragma unroll
    for (int c = 0; c < 8; c++) acc += spart[c * MAXN + node];
    float my = tanhf(acc * winv);
    score[node] = my;
    s[t] = my;
    __syncthreads();
    int rank = 0;
    for (int j = 0; j < npg; j++) {
        float v = s[j];
        rank += (v > my) || (v == my && j < t);
    }
    if (rank < k) {
        newid[node] = g * k + rank;
        perm[g * k + rank] = node;
    } else {
        newid[node] = -1;
    }
}

// ---------------- fused gather*score + readout [max | mean] ----------------
__global__ void gather_readout_kernel(const float* __restrict__ x,
                                      const float* __restrict__ score,
                                      const int* __restrict__ perm,
                                      float* __restrict__ nx,
                                      float* __restrict__ ro,
                                      int k, int accumulate) {
    int g = blockIdx.x, f = threadIdx.x;  // 256 threads
    float mx = -3.4e38f, sum = 0.f;
    #pragma unroll 2
    for (int j = 0; j < k; j++) {
        int old = __ldg(&perm[g * k + j]);
        float sc = __ldg(&score[old]);
        float v = x[(size_t)old * 256 + f] * sc;
        nx[((size_t)g * k + j) * 256 + f] = v;
        mx = fmaxf(mx, v);
        sum += v;
    }
    float mean = sum / (float)k;
    if (accumulate) {
        ro[g*512 + f]       += mx;
        ro[g*512 + 256 + f] += mean;
    } else {
        ro[g*512 + f]       = mx;
        ro[g*512 + 256 + f] = mean;
    }
}

__global__ void remap_kernel(const int* __restrict__ src, const int* __restrict__ dst,
                             const float* __restrict__ ew, const int* __restrict__ newid,
                             int* __restrict__ nsrc, int* __restrict__ ndst,
                             float* __restrict__ new_ew, int E) {
    int e = blockIdx.x * blockDim.x + threadIdx.x;
    if (e >= E) return;
    int s = newid[src[e]], d = newid[dst[e]];
    float w = ew ? ew[e] : 1.0f;
    bool valid = (s >= 0) && (d >= 0);
    nsrc[e]   = valid ? s : 0;
    ndst[e]   = valid ? d : 0;
    new_ew[e] = valid ? w : 0.f;
}

// ---------------- MLP (multi-graph blocks to amortize weight reads) ------------
__global__ __launch_bounds__(256) void lin1_kernel(const float* __restrict__ in,
        const float* __restrict__ W, const float* __restrict__ b,
        float* __restrict__ out) {
    int gb = blockIdx.x * 8, c = threadIdx.x;   // grid 32, block 256
    __shared__ float rows[8 * 512];
    for (int i = c; i < 8 * 512; i += 256) rows[i] = in[gb * 512 + i];
    __syncthreads();
    float acc[8];
    float bc = b[c];
    #pragma unroll
    for (int gg = 0; gg < 8; gg++) acc[gg] = bc;
    for (int kk = 0; kk < 512; kk++) {
        float wv = W[kk * 256 + c];
        #pragma unroll
        for (int gg = 0; gg < 8; gg++) acc[gg] += rows[gg * 512 + kk] * wv;
    }
    #pragma unroll
    for (int gg = 0; gg < 8; gg++)
        out[(gb + gg) * 256 + c] = fmaxf(acc[gg], 0.f);
}
__global__ __launch_bounds__(128) void lin2_kernel(const float* __restrict__ in,
        const float* __restrict__ W, const float* __restrict__ b,
        float* __restrict__ out) {
    int gb = blockIdx.x * 16, c = threadIdx.x;  // grid 16, block 128
    __shared__ float rows[16 * 256];
    for (int i = c; i < 16 * 256; i += 128) rows[i] = in[gb * 256 + i];
    __syncthreads();
    float acc[16];
    float bc = b[c];
    #pragma unroll
    for (int gg = 0; gg < 16; gg++) acc[gg] = bc;
    for (int kk = 0; kk < 256; kk++) {
        float wv = W[kk * 128 + c];
        #pragma unroll
        for (int gg = 0; gg < 16; gg++) acc[gg] += rows[gg * 256 + kk] * wv;
    }
    #pragma unroll
    for (int gg = 0; gg < 16; gg++)
        out[(gb + gg) * 128 + c] = fmaxf(acc[gg], 0.f);
}
__global__ void lin3_lsm_kernel(const float* __restrict__ in, const float* __restrict__ W,
                                const float* __restrict__ b, float* __restrict__ out) {
    int g = blockIdx.x, lane = threadIdx.x;
    const float* row = in + g*128;
    float a0 = 0.f, a1 = 0.f;
    #pragma unroll
    for (int kk = lane; kk < 128; kk += 32) {
        float v = row[kk];
        a0 += v * W[kk*2 + 0];
        a1 += v * W[kk*2 + 1];
    }
    #pragma unroll
    for (int o = 16; o > 0; o >>= 1) {
        a0 += __shfl_down_sync(0xFFFFFFFFu, a0, o);
        a1 += __shfl_down_sync(0xFFFFFFFFu, a1, o);
    }
    if (lane == 0) {
        float l0 = a0 + b[0], l1 = a1 + b[1];
        float m = fmaxf(l0, l1);
        float lse = m + logf(expf(l0 - m) + expf(l1 - m));
        out[g*2 + 0] = l0 - lse;
        out[g*2 + 1] = l1 - lse;
    }
}

// ---------------- host driver ----------------
extern "C" void kernel_launch(void* const* d_in, const int* in_sizes, int n_in,
                              void* d_out, int out_size) {
    const float* d_x      = (const float*)d_in[0];
    const int*   d_ei     = (const int*)d_in[1];
    const float* gcn_w0   = (const float*)d_in[3];
    const float* gcn_b0   = (const float*)d_in[4];
    const float* gcn_w1   = (const float*)d_in[5];
    const float* gcn_b1   = (const float*)d_in[6];
    const float* gcn_w2   = (const float*)d_in[7];
    const float* gcn_b2   = (const float*)d_in[8];
    const float* pool_w0  = (const float*)d_in[9];
    const float* pool_w1  = (const float*)d_in[10];
    const float* pool_w2  = (const float*)d_in[11];
    const float* lin1_w   = (const float*)d_in[12];
    const float* lin1_b   = (const float*)d_in[13];
    const float* lin2_w   = (const float*)d_in[14];
    const float* lin2_b   = (const float*)d_in[15];
    const float* lin3_w   = (const float*)d_in[16];
    const float* lin3_b   = (const float*)d_in[17];
    float* out = (float*)d_out;

    const int E = in_sizes[1] / 2;
    const int* d_src = d_ei;
    const int* d_dst = d_ei + E;

    float *p_h, *p_agg, *p_x, *p_dinv, *p_score, *p_spart, *p_ro, *p_h1, *p_h2;
    int *p_newid, *p_perm, *p_es0, *p_ed0, *p_es1, *p_ed1, *p_rs, *p_rc;
    int2 *p_cpack;
    float *p_ew0, *p_ew1;
    __nv_bfloat16 *p_whi, *p_wmid, *p_wlo;
    cudaGetSymbolAddress((void**)&p_h,    g_h);
    cudaGetSymbolAddress((void**)&p_agg,  g_agg);
    cudaGetSymbolAddress((void**)&p_x,    g_x);
    cudaGetSymbolAddress((void**)&p_dinv, g_dinv);
    cudaGetSymbolAddress((void**)&p_score,g_score);
    cudaGetSymbolAddress((void**)&p_spart,g_spart);
    cudaGetSymbolAddress((void**)&p_newid,g_newid);
    cudaGetSymbolAddress((void**)&p_perm, g_perm);
    cudaGetSymbolAddress((void**)&p_es0,  g_esrc0);
    cudaGetSymbolAddress((void**)&p_ed0,  g_edst0);
    cudaGetSymbolAddress((void**)&p_ew0,  g_eew0);
    cudaGetSymbolAddress((void**)&p_es1,  g_esrc1);
    cudaGetSymbolAddress((void**)&p_ed1,  g_edst1);
    cudaGetSymbolAddress((void**)&p_ew1,  g_eew1);
    cudaGetSymbolAddress((void**)&p_rs,   g_rs);
    cudaGetSymbolAddress((void**)&p_rc,   g_rc);
    cudaGetSymbolAddress((void**)&p_cpack,g_cpack);
    cudaGetSymbolAddress((void**)&p_ro,   g_ro);
    cudaGetSymbolAddress((void**)&p_h1,   g_h1);
    cudaGetSymbolAddress((void**)&p_h2,   g_h2);
    cudaGetSymbolAddress((void**)&p_whi,  g_whi);
    cudaGetSymbolAddress((void**)&p_wmid, g_wmid);
    cudaGetSymbolAddress((void**)&p_wlo,  g_wlo);

    // ---------------- level 0 ----------------
    int n = MAXN;                 // 65536 nodes
    {
        int npg = 256;
        wsplit_kernel<<<128, 256>>>(gcn_w0, 128, p_whi, p_wmid, p_wlo);
        gemm_mma_kernel<<<dim3(n / 128, 2), 256, MMA_SMEM>>>(d_x, p_whi, p_wmid, p_wlo, p_h, 128);
        csr_build_kernel<<<G, 256>>>(d_src, d_dst, nullptr, npg,
                                     p_rs, p_rc, p_cpack, p_dinv);
        agg_fused_kernel<<<dim3(8, G), 256, npg*32*4>>>(p_h, p_dinv, p_rs, p_rc,
                                                        p_cpack, gcn_b0, pool_w0,
                                                        p_agg, p_spart, npg);
    }
    // pool 0: npg=256 -> k=128
    {
        int npg = 256, k = 128, nNew = G * k;
        pool_kernel<<<G, npg>>>(p_spart, pool_w0, p_score, npg, k, p_newid, p_perm);
        gather_readout_kernel<<<G, 256>>>(p_agg, p_score, p_perm, p_x, p_ro, k, 0);
        remap_kernel<<<(E + 255) / 256, 256>>>(d_src, d_dst, nullptr, p_newid,
                                               p_es0, p_ed0, p_ew0, E);
        n = nNew;                 // 32768
    }
    // ---------------- level 1 ----------------
    {
        int npg = 128;
        wsplit_kernel<<<256, 256>>>(gcn_w1, 256, p_whi, p_wmid, p_wlo);
        gemm_mma_kernel<<<dim3(n / 128, 2), 256, MMA_SMEM>>>(p_x, p_whi, p_wmid, p_wlo, p_h, 256);
        csr_build_kernel<<<G, 256>>>(p_es0, p_ed0, p_ew0, npg,
                                     p_rs, p_rc, p_cpack, p_dinv);
        agg_fused_kernel<<<dim3(8, G), 256, npg*32*4>>>(p_h, p_dinv, p_rs, p_rc,
                                                        p_cpack, gcn_b1, pool_w1,
                                                        p_agg, p_spart, npg);
    }
    {
        int npg = 128, k = 64, nNew = G * k;
        pool_kernel<<<G, npg>>>(p_spart, pool_w1, p_score, npg, k, p_newid, p_perm);
        gather_readout_kernel<<<G, 256>>>(p_agg, p_score, p_perm, p_x, p_ro, k, 1);
        remap_kernel<<<(E + 255) / 256, 256>>>(p_es0, p_ed0, p_ew0, p_newid,
                                               p_es1, p_ed1, p_ew1, E);
        n = nNew;                 // 16384
    }
    // ---------------- level 2 ----------------
    {
        int npg = 64;
        wsplit_kernel<<<256, 256>>>(gcn_w2, 256, p_whi, p_wmid, p_wlo);
        gemm_mma_kernel<<<dim3(n / 128, 2), 256, MMA_SMEM>>>(p_x, p_whi, p_wmid, p_wlo, p_h, 256);
        csr_build_kernel<<<G, 256>>>(p_es1, p_ed1, p_ew1, npg,
                                     p_rs, p_rc, p_cpack, p_dinv);
        agg_fused_kernel<<<dim3(8, G), 256, npg*32*4>>>(p_h, p_dinv, p_rs, p_rc,
                                                        p_cpack, gcn_b2, pool_w2,
                                                        p_agg, p_spart, npg);
    }
    {
        int npg = 64, k = 32;
        pool_kernel<<<G, npg>>>(p_spart, pool_w2, p_score, npg, k, p_newid, p_perm);
        gather_readout_kernel<<<G, 256>>>(p_agg, p_score, p_perm, p_x, p_ro, k, 1);
    }

    // ---------------- MLP head ----------------
    lin1_kernel<<<32, 256>>>(p_ro, lin1_w, lin1_b, p_h1);
    lin2_kernel<<<16, 128>>>(p_h1, lin2_w, lin2_b, p_h2);
    lin3_lsm_kernel<<<G, 32>>>(p_h2, lin3_w, lin3_b, out);
}

// round 7
// speedup vs baseline: 1.1679x; 1.1679x over previous
#include <cuda_runtime.h>
#include <cuda_fp16.h>
#include <cuda_bf16.h>
#include <math.h>
#include <stdint.h>

// Problem constants
#define G 256
#define N0 256
#define HF 256            // hidden feature dim
#define MAXN (G*N0)       // 65536
#define MAXE (G*2048)     // 524288
#define EPG 2048          // edges per graph (fixed slot count, masked edges have ew=0)

// -------- scratch (device globals; no allocation allowed) --------
__device__ float g_h[MAXN*HF];        // 64 MB : h = x @ W
__device__ float g_agg[MAXN*HF];      // 64 MB : conv output
__device__ float g_x[(MAXN/2)*HF];    // 32 MB : pooled features
__device__ float g_dinv[MAXN];
__device__ float g_score[MAXN];
__device__ int   g_newid[MAXN];
__device__ int   g_perm[MAXN/2];
__device__ int   g_esrc0[MAXE], g_edst0[MAXE];
__device__ float g_eew0[MAXE];
__device__ int   g_esrc1[MAXE], g_edst1[MAXE];
__device__ float g_eew1[MAXE];
__device__ int   g_rs[MAXN];
__device__ int   g_rc[MAXN];
__device__ int2  g_cpack[MAXE];       // CSR packed (src, norm-bits)
__device__ float g_ro[G*512];
__device__ float g_h1[G*256];
__device__ float g_h2[G*128];
__device__ float g_winv;
// X split buffers (fp16 hi/lo), max 65536*128 = 32768*256 = 8.4M elements
__device__ __half g_xhi[8388608];
__device__ __half g_xlo[8388608];
// W split buffers (fp16 hi/lo, [256 (N)] x [K] K-major), K<=256
__device__ __half g_whi[256*256];
__device__ __half g_wlo[256*256];

// ================= helpers =================
__device__ __forceinline__ uint32_t smem_u32(const void* p) {
    uint32_t a;
    asm("{ .reg .u64 t; cvta.to.shared.u64 t, %1; cvt.u32.u64 %0, t; }"
        : "=r"(a) : "l"(p));
    return a;
}
__device__ __forceinline__ void ldsm_x4(uint32_t* r, uint32_t addr) {
    asm volatile("ldmatrix.sync.aligned.m8n8.x4.shared.b16 {%0,%1,%2,%3}, [%4];"
        : "=r"(r[0]), "=r"(r[1]), "=r"(r[2]), "=r"(r[3]) : "r"(addr));
}
__device__ __forceinline__ void ldsm_x2(uint32_t* r, uint32_t addr) {
    asm volatile("ldmatrix.sync.aligned.m8n8.x2.shared.b16 {%0,%1}, [%2];"
        : "=r"(r[0]), "=r"(r[1]) : "r"(addr));
}
__device__ __forceinline__ void mma_f16(float* d, const uint32_t* a, const uint32_t* b) {
    asm volatile("mma.sync.aligned.m16n8k16.row.col.f32.f16.f16.f32 "
        "{%0,%1,%2,%3}, {%4,%5,%6,%7}, {%8,%9}, {%0,%1,%2,%3};"
        : "+f"(d[0]), "+f"(d[1]), "+f"(d[2]), "+f"(d[3])
        : "r"(a[0]), "r"(a[1]), "r"(a[2]), "r"(a[3]), "r"(b[0]), "r"(b[1]));
}

// ================= split pre-passes (fp16 2-way) =================
__global__ void xsplit_kernel(const float* __restrict__ X, int total,
                              __half* __restrict__ xhi, __half* __restrict__ xlo) {
    int i = blockIdx.x * 256 + threadIdx.x;
    if (i >= total) return;
    float v = X[i];
    __half h = __float2half_rn(v);
    __half l = __float2half_rn(v - __half2float(h));
    xhi[i] = h; xlo[i] = l;
}

__global__ void wsplit_kernel(const float* __restrict__ W, int K,
                              __half* __restrict__ whi, __half* __restrict__ wlo) {
    int idx = blockIdx.x * 256 + threadIdx.x;
    if (idx >= K * 256) return;
    int k = idx >> 8, n = idx & 255;
    float w = W[idx];
    __half h = __float2half_rn(w);
    __half l = __float2half_rn(w - __half2float(h));
    whi[n*K + k] = h; wlo[n*K + k] = l;
}

// ================= MMA GEMM: C[n,256] = X[n,K] @ W[K,256] =================
// near-fp32 via fp16 2-way split, 4 product segments (hh, hl, lh, ll).
// CTA 128x128 (grid.y covers N=256); 8 warps of 64x32 tiles.
// SMEM per seg tile: 128 rows x 24 halves stride (48B) = 6144 B.
#define SEGB 6144
#define MMA_SMEM (4*SEGB)

__global__ __launch_bounds__(256) void gemm_mma_kernel(
        const __half* __restrict__ Xhi, const __half* __restrict__ Xlo,
        const __half* __restrict__ Whi, const __half* __restrict__ Wlo,
        float* __restrict__ C, int K) {
    extern __shared__ __align__(16) char smem[];
    char* smA = smem;                  // 2 segs
    char* smB = smem + 2*SEGB;         // 2 segs
    uint32_t sb = smem_u32(smem);
    int tid = threadIdx.x, w = tid >> 5, lane = tid & 31;
    int rowBase = blockIdx.x * 128, colBase = blockIdx.y * 128;
    int warpRow = (w >> 2) * 64, warpCol = (w & 3) * 32;

    float acc[4][4][4];
    #pragma unroll
    for (int i = 0; i < 4; i++)
        #pragma unroll
        for (int j = 0; j < 4; j++)
            #pragma unroll
            for (int d = 0; d < 4; d++) acc[i][j][d] = 0.f;

    int r  = tid >> 1;                  // 0..127
    int hf = tid & 1;                   // 8-half (16B) half-row
    uint32_t stOff = (uint32_t)(r * 48 + hf * 16);

    int bl = lane & 15;
    uint32_t aFragBase = sb + (uint32_t)((warpRow + (lane & 15)) * 48 + (lane >> 4) * 16);
    uint32_t bFragBase = sb + 2*SEGB
                       + (uint32_t)((warpCol + (bl & 7)) * 48 + (bl >> 3) * 16);

    const int NC = K >> 4;
    for (int kb = 0; kb < NC; kb++) {
        // stage A (pre-split fp16, plain copies)
        {
            size_t goff = (size_t)(rowBase + r) * K + kb * 16 + hf * 8;
            *(uint4*)(smA        + stOff) = *(const uint4*)(Xhi + goff);
            *(uint4*)(smA + SEGB + stOff) = *(const uint4*)(Xlo + goff);
        }
        // stage B (pre-split fp16 [n][K] K-major)
        {
            size_t goff = (size_t)(colBase + r) * K + kb * 16 + hf * 8;
            *(uint4*)(smB        + stOff) = *(const uint4*)(Whi + goff);
            *(uint4*)(smB + SEGB + stOff) = *(const uint4*)(Wlo + goff);
        }
        __syncthreads();

        uint32_t bfr[2][4][2];
        #pragma unroll
        for (int s = 0; s < 2; s++)
            #pragma unroll
            for (int nt = 0; nt < 4; nt++)
                ldsm_x2(bfr[s][nt], bFragBase + s*SEGB + nt*(8*48));

        #pragma unroll
        for (int mt = 0; mt < 4; mt++) {
            uint32_t afr[2][4];
            #pragma unroll
            for (int s = 0; s < 2; s++)
                ldsm_x4(afr[s], aFragBase + s*SEGB + mt*(16*48));
            #pragma unroll
            for (int cb = 0; cb < 4; cb++) {        // hh, hl, lh, ll
                int ai = cb >> 1, bi = cb & 1;
                #pragma unroll
                for (int nt = 0; nt < 4; nt++)
                    mma_f16(acc[mt][nt], afr[ai], bfr[bi][nt]);
            }
        }
        __syncthreads();
    }

    #pragma unroll
    for (int mt = 0; mt < 4; mt++) {
        int row = rowBase + warpRow + mt*16 + (lane >> 2);
        #pragma unroll
        for (int nt = 0; nt < 4; nt++) {
            int col = colBase + warpCol + nt*8 + (lane & 3)*2;
            *(float2*)&C[(size_t)row * 256 + col] =
                make_float2(acc[mt][nt][0], acc[mt][nt][1]);
            *(float2*)&C[(size_t)(row + 8) * 256 + col] =
                make_float2(acc[mt][nt][2], acc[mt][nt][3]);
        }
    }
}

// ---------------- per-graph CSR build (block = graph, 256 threads) ----------------
__global__ __launch_bounds__(256) void csr_build_kernel(
        const int* __restrict__ src, const int* __restrict__ dst,
        const float* __restrict__ ew, int npg,
        int* __restrict__ rs, int* __restrict__ rc,
        int2* __restrict__ cpack, float* __restrict__ dinv) {
    __shared__ float sdeg[256];
    __shared__ int   scnt[256];
    __shared__ int   sscan[256];
    __shared__ int   spos[256];
    int g = blockIdx.x, t = threadIdx.x;
    int nbase = g * npg, ebase = g * EPG;

    if (t < npg) { sdeg[t] = 1.0f; scnt[t] = 0; }
    __syncthreads();
    for (int e = t; e < EPG; e += 256) {
        float w = ew ? ew[ebase + e] : 1.0f;
        if (w != 0.f) {
            int d = dst[ebase + e] - nbase;
            atomicAdd(&sdeg[d], w);
            atomicAdd(&scnt[d], 1);
        }
    }
    __syncthreads();
    int v = (t < npg) ? scnt[t] : 0;
    sscan[t] = v;
    __syncthreads();
    #pragma unroll
    for (int off = 1; off < 256; off <<= 1) {
        int add = (t >= off) ? sscan[t - off] : 0;
        __syncthreads();
        sscan[t] += add;
        __syncthreads();
    }
    int start = sscan[t] - v;
    if (t < npg) {
        rs[nbase + t] = start;
        rc[nbase + t] = v;
        spos[t] = start;
        dinv[nbase + t] = 1.0f / sdeg[t];
    }
    __syncthreads();
    for (int e = t; e < EPG; e += 256) {
        float w = ew ? ew[ebase + e] : 1.0f;
        if (w != 0.f) {
            int s = src[ebase + e] - nbase;
            int d = dst[ebase + e] - nbase;
            float nm = rsqrtf(sdeg[s]) * rsqrtf(sdeg[d]) * w;
            int idx = atomicAdd(&spos[d], 1);
            cpack[ebase + idx] = make_int2(s, __float_as_int(nm));
        }
    }
}

// ---------------- fused aggregation + self-loop + bias + relu ----------------
// block = (fc in [0,4), graph g); stages h tile [npg][64] in smem
__global__ __launch_bounds__(256) void agg_fused_kernel(
        const float* __restrict__ h, const float* __restrict__ dinv,
        const int* __restrict__ rs, const int* __restrict__ rc,
        const int2* __restrict__ cpack, const float* __restrict__ bias,
        float* __restrict__ out, int npg) {
    extern __shared__ float ht[];   // npg * 64 floats
    int fc = blockIdx.x, g = blockIdx.y;
    int t = threadIdx.x;
    int nbase = g * npg, ebase = g * EPG;

    const float4* h4 = (const float4*)h;
    float4* ht4 = (float4*)ht;
    for (int i = t; i < npg * 16; i += 256) {
        int node = i >> 4, q = i & 15;
        ht4[i] = h4[(size_t)(nbase + node) * 64 + fc * 16 + q];
    }
    __syncthreads();

    int w = t >> 5, lane = t & 31;
    float b0 = __ldg(bias + fc*64 + lane*2);
    float b1 = __ldg(bias + fc*64 + lane*2 + 1);
    for (int d = w; d < npg; d += 8) {
        float dv = dinv[nbase + d];
        float a0 = ht[d*64 + lane*2]     * dv + b0;
        float a1 = ht[d*64 + lane*2 + 1] * dv + b1;
        int cnt = rc[nbase + d];
        const int2* cp = cpack + ebase + rs[nbase + d];
        int e = 0;
        for (; e + 4 <= cnt; e += 4) {
            int2 p0 = __ldg(cp + e);
            int2 p1 = __ldg(cp + e + 1);
            int2 p2 = __ldg(cp + e + 2);
            int2 p3 = __ldg(cp + e + 3);
            a0 += __int_as_float(p0.y) * ht[p0.x*64 + lane*2];
            a1 += __int_as_float(p0.y) * ht[p0.x*64 + lane*2 + 1];
            a0 += __int_as_float(p1.y) * ht[p1.x*64 + lane*2];
            a1 += __int_as_float(p1.y) * ht[p1.x*64 + lane*2 + 1];
            a0 += __int_as_float(p2.y) * ht[p2.x*64 + lane*2];
            a1 += __int_as_float(p2.y) * ht[p2.x*64 + lane*2 + 1];
            a0 += __int_as_float(p3.y) * ht[p3.x*64 + lane*2];
            a1 += __int_as_float(p3.y) * ht[p3.x*64 + lane*2 + 1];
        }
        for (; e < cnt; e++) {
            int2 p = __ldg(cp + e);
            a0 += __int_as_float(p.y) * ht[p.x*64 + lane*2];
            a1 += __int_as_float(p.y) * ht[p.x*64 + lane*2 + 1];
        }
        float2 o;
        o.x = fmaxf(a0, 0.f);
        o.y = fmaxf(a1, 0.f);
        *(float2*)(out + (size_t)(nbase + d) * 256 + fc*64 + lane*2) = o;
    }
}

// ---------------- pooling ----------------
__global__ void wnorm_kernel(const float* __restrict__ w) {
    __shared__ float red[256];
    int t = threadIdx.x;
    float v = w[t];
    red[t] = v * v;
    __syncthreads();
    for (int s = 128; s > 0; s >>= 1) {
        if (t < s) red[t] += red[t + s];
        __syncthreads();
    }
    if (t == 0) g_winv = rsqrtf(red[0]);
}

__global__ void score_kernel(const float* __restrict__ x, const float* __restrict__ w,
                             float* __restrict__ score, int n) {
    int gt = blockIdx.x * blockDim.x + threadIdx.x;
    int node = gt >> 5, lane = gt & 31;
    if (node >= n) return;
    const float* row = x + (size_t)node * HF;
    float s = 0.f;
    #pragma unroll
    for (int f = lane; f < HF; f += 32) s += row[f] * w[f];
    #pragma unroll
    for (int o = 16; o > 0; o >>= 1) s += __shfl_down_sync(0xFFFFFFFFu, s, o);
    if (lane == 0) score[node] = tanhf(s * g_winv);
}

__global__ void pool_kernel(const float* __restrict__ score, int npg, int k,
                            int* __restrict__ newid, int* __restrict__ perm) {
    __shared__ float s[256];
    int g = blockIdx.x, t = threadIdx.x;
    int node = g * npg + t;
    float my = score[node];
    s[t] = my;
    __syncthreads();
    int rank = 0;
    for (int j = 0; j < npg; j++) {
        float v = s[j];
        rank += (v > my) || (v == my && j < t);
    }
    if (rank < k) {
        newid[node] = g * k + rank;
        perm[g * k + rank] = node;
    } else {
        newid[node] = -1;
    }
}

__global__ void gather_scale_kernel(const float* __restrict__ x, const float* __restrict__ score,
                                    const int* __restrict__ perm, float* __restrict__ nx, int nNew) {
    int i = blockIdx.x * blockDim.x + threadIdx.x;
    if (i >= nNew * HF) return;
    int nn = i >> 8, f = i & 255;
    int old = perm[nn];
    nx[i] = x[(size_t)old * HF + f] * score[old];
}

__global__ void remap_kernel(const int* __restrict__ src, const int* __restrict__ dst,
                             const float* __restrict__ ew, const int* __restrict__ newid,
                             int* __restrict__ nsrc, int* __restrict__ ndst,
                             float* __restrict__ new_ew, int E) {
    int e = blockIdx.x * blockDim.x + threadIdx.x;
    if (e >= E) return;
    int s = newid[src[e]], d = newid[dst[e]];
    float w = ew ? ew[e] : 1.0f;
    bool valid = (s >= 0) && (d >= 0);
    nsrc[e]   = valid ? s : 0;
    ndst[e]   = valid ? d : 0;
    new_ew[e] = valid ? w : 0.f;
}

// ---------------- readout: [max | mean] per graph ----------------
__global__ void readout_kernel(const float* __restrict__ x, int k,
                               float* __restrict__ ro, int accumulate) {
    int g = blockIdx.x, f = threadIdx.x;
    const float* base = x + (size_t)g * k * HF + f;
    float mx = -3.4e38f, sum = 0.f;
    for (int j = 0; j < k; j++) {
        float v = base[(size_t)j * HF];
        mx = fmaxf(mx, v);
        sum += v;
    }
    float mean = sum / (float)k;
    if (accumulate) {
        ro[g*512 + f]       += mx;
        ro[g*512 + 256 + f] += mean;
    } else {
        ro[g*512 + f]       = mx;
        ro[g*512 + 256 + f] = mean;
    }
}

// ---------------- MLP (multi-graph blocks to amortize weight reads) ------------
__global__ __launch_bounds__(256) void lin1_kernel(const float* __restrict__ in,
        const float* __restrict__ W, const float* __restrict__ b,
        float* __restrict__ out) {
    int gb = blockIdx.x * 8, c = threadIdx.x;   // grid 32, block 256
    __shared__ float rows[8 * 512];
    for (int i = c; i < 8 * 512; i += 256) rows[i] = in[gb * 512 + i];
    __syncthreads();
    float acc[8];
    float bc = b[c];
    #pragma unroll
    for (int gg = 0; gg < 8; gg++) acc[gg] = bc;
    for (int kk = 0; kk < 512; kk++) {
        float wv = W[kk * 256 + c];
        #pragma unroll
        for (int gg = 0; gg < 8; gg++) acc[gg] += rows[gg * 512 + kk] * wv;
    }
    #pragma unroll
    for (int gg = 0; gg < 8; gg++)
        out[(gb + gg) * 256 + c] = fmaxf(acc[gg], 0.f);
}
__global__ __launch_bounds__(128) void lin2_kernel(const float* __restrict__ in,
        const float* __restrict__ W, const float* __restrict__ b,
        float* __restrict__ out) {
    int gb = blockIdx.x * 16, c = threadIdx.x;  // grid 16, block 128
    __shared__ float rows[16 * 256];
    for (int i = c; i < 16 * 256; i += 128) rows[i] = in[gb * 256 + i];
    __syncthreads();
    float acc[16];
    float bc = b[c];
    #pragma unroll
    for (int gg = 0; gg < 16; gg++) acc[gg] = bc;
    for (int kk = 0; kk < 256; kk++) {
        float wv = W[kk * 128 + c];
        #pragma unroll
        for (int gg = 0; gg < 16; gg++) acc[gg] += rows[gg * 256 + kk] * wv;
    }
    #pragma unroll
    for (int gg = 0; gg < 16; gg++)
        out[(gb + gg) * 128 + c] = fmaxf(acc[gg], 0.f);
}
__global__ void lin3_lsm_kernel(const float* __restrict__ in, const float* __restrict__ W,
                                const float* __restrict__ b, float* __restrict__ out) {
    int g = blockIdx.x, lane = threadIdx.x;
    const float* row = in + g*128;
    float a0 = 0.f, a1 = 0.f;
    #pragma unroll
    for (int kk = lane; kk < 128; kk += 32) {
        float v = row[kk];
        a0 += v * W[kk*2 + 0];
        a1 += v * W[kk*2 + 1];
    }
    #pragma unroll
    for (int o = 16; o > 0; o >>= 1) {
        a0 += __shfl_down_sync(0xFFFFFFFFu, a0, o);
        a1 += __shfl_down_sync(0xFFFFFFFFu, a1, o);
    }
    if (lane == 0) {
        float l0 = a0 + b[0], l1 = a1 + b[1];
        float m = fmaxf(l0, l1);
        float lse = m + logf(expf(l0 - m) + expf(l1 - m));
        out[g*2 + 0] = l0 - lse;
        out[g*2 + 1] = l1 - lse;
    }
}

// ---------------- host driver ----------------
extern "C" void kernel_launch(void* const* d_in, const int* in_sizes, int n_in,
                              void* d_out, int out_size) {
    const float* d_x      = (const float*)d_in[0];
    const int*   d_ei     = (const int*)d_in[1];
    const float* gcn_w0   = (const float*)d_in[3];
    const float* gcn_b0   = (const float*)d_in[4];
    const float* gcn_w1   = (const float*)d_in[5];
    const float* gcn_b1   = (const float*)d_in[6];
    const float* gcn_w2   = (const float*)d_in[7];
    const float* gcn_b2   = (const float*)d_in[8];
    const float* pool_w0  = (const float*)d_in[9];
    const float* pool_w1  = (const float*)d_in[10];
    const float* pool_w2  = (const float*)d_in[11];
    const float* lin1_w   = (const float*)d_in[12];
    const float* lin1_b   = (const float*)d_in[13];
    const float* lin2_w   = (const float*)d_in[14];
    const float* lin2_b   = (const float*)d_in[15];
    const float* lin3_w   = (const float*)d_in[16];
    const float* lin3_b   = (const float*)d_in[17];
    float* out = (float*)d_out;

    const int E = in_sizes[1] / 2;
    const int* d_src = d_ei;
    const int* d_dst = d_ei + E;

    float *p_h, *p_agg, *p_x, *p_dinv, *p_score, *p_ro, *p_h1, *p_h2;
    int *p_newid, *p_perm, *p_es0, *p_ed0, *p_es1, *p_ed1, *p_rs, *p_rc;
    int2 *p_cpack;
    float *p_ew0, *p_ew1;
    __half *p_xhi, *p_xlo, *p_whi, *p_wlo;
    cudaGetSymbolAddress((void**)&p_h,    g_h);
    cudaGetSymbolAddress((void**)&p_agg,  g_agg);
    cudaGetSymbolAddress((void**)&p_x,    g_x);
    cudaGetSymbolAddress((void**)&p_dinv, g_dinv);
    cudaGetSymbolAddress((void**)&p_score,g_score);
    cudaGetSymbolAddress((void**)&p_newid,g_newid);
    cudaGetSymbolAddress((void**)&p_perm, g_perm);
    cudaGetSymbolAddress((void**)&p_es0,  g_esrc0);
    cudaGetSymbolAddress((void**)&p_ed0,  g_edst0);
    cudaGetSymbolAddress((void**)&p_ew0,  g_eew0);
    cudaGetSymbolAddress((void**)&p_es1,  g_esrc1);
    cudaGetSymbolAddress((void**)&p_ed1,  g_edst1);
    cudaGetSymbolAddress((void**)&p_ew1,  g_eew1);
    cudaGetSymbolAddress((void**)&p_rs,   g_rs);
    cudaGetSymbolAddress((void**)&p_rc,   g_rc);
    cudaGetSymbolAddress((void**)&p_cpack,g_cpack);
    cudaGetSymbolAddress((void**)&p_ro,   g_ro);
    cudaGetSymbolAddress((void**)&p_h1,   g_h1);
    cudaGetSymbolAddress((void**)&p_h2,   g_h2);
    cudaGetSymbolAddress((void**)&p_xhi,  g_xhi);
    cudaGetSymbolAddress((void**)&p_xlo,  g_xlo);
    cudaGetSymbolAddress((void**)&p_whi,  g_whi);
    cudaGetSymbolAddress((void**)&p_wlo,  g_wlo);

    cudaFuncSetAttribute(agg_fused_kernel,
                         cudaFuncAttributeMaxDynamicSharedMemorySize, 65536);

    // ---------------- level 0 ----------------
    int n = MAXN;                 // 65536 nodes
    {
        int npg = 256;
        wsplit_kernel<<<128, 256>>>(gcn_w0, 128, p_whi, p_wlo);
        xsplit_kernel<<<(n * 128 + 255) / 256, 256>>>(d_x, n * 128, p_xhi, p_xlo);
        gemm_mma_kernel<<<dim3(n / 128, 2), 256, MMA_SMEM>>>(p_xhi, p_xlo, p_whi, p_wlo, p_h, 128);
        csr_build_kernel<<<G, 256>>>(d_src, d_dst, nullptr, npg,
                                     p_rs, p_rc, p_cpack, p_dinv);
        agg_fused_kernel<<<dim3(4, G), 256, npg*64*4>>>(p_h, p_dinv, p_rs, p_rc,
                                                        p_cpack, gcn_b0, p_agg, npg);
    }
    // pool 0: npg=256 -> k=128
    {
        int npg = 256, k = 128, nNew = G * k;
        wnorm_kernel<<<1, 256>>>(pool_w0);
        score_kernel<<<(n * 32 + 255) / 256, 256>>>(p_agg, pool_w0, p_score, n);
        pool_kernel<<<G, npg>>>(p_score, npg, k, p_newid, p_perm);
        gather_scale_kernel<<<(nNew * HF + 255) / 256, 256>>>(p_agg, p_score, p_perm, p_x, nNew);
        remap_kernel<<<(E + 255) / 256, 256>>>(d_src, d_dst, nullptr, p_newid,
                                               p_es0, p_ed0, p_ew0, E);
        readout_kernel<<<G, 256>>>(p_x, k, p_ro, 0);
        n = nNew;                 // 32768
    }
    // ---------------- level 1 ----------------
    {
        int npg = 128;
        wsplit_kernel<<<256, 256>>>(gcn_w1, 256, p_whi, p_wlo);
        xsplit_kernel<<<(n * 256 + 255) / 256, 256>>>(p_x, n * 256, p_xhi, p_xlo);
        gemm_mma_kernel<<<dim3(n / 128, 2), 256, MMA_SMEM>>>(p_xhi, p_xlo, p_whi, p_wlo, p_h, 256);
        csr_build_kernel<<<G, 256>>>(p_es0, p_ed0, p_ew0, npg,
                                     p_rs, p_rc, p_cpack, p_dinv);
        agg_fused_kernel<<<dim3(4, G), 256, npg*64*4>>>(p_h, p_dinv, p_rs, p_rc,
                                                        p_cpack, gcn_b1, p_agg, npg);
    }
    {
        int npg = 128, k = 64, nNew = G * k;
        wnorm_kernel<<<1, 256>>>(pool_w1);
        score_kernel<<<(n * 32 + 255) / 256, 256>>>(p_agg, pool_w1, p_score, n);
        pool_kernel<<<G, npg>>>(p_score, npg, k, p_newid, p_perm);
        gather_scale_kernel<<<(nNew * HF + 255) / 256, 256>>>(p_agg, p_score, p_perm, p_x, nNew);
        remap_kernel<<<(E + 255) / 256, 256>>>(p_es0, p_ed0, p_ew0, p_newid,
                                               p_es1, p_ed1, p_ew1, E);
        readout_kernel<<<G, 256>>>(p_x, k, p_ro, 1);
        n = nNew;                 // 16384
    }
    // ---------------- level 2 ----------------
    {
        int npg = 64;
        wsplit_kernel<<<256, 256>>>(gcn_w2, 256, p_whi, p_wlo);
        xsplit_kernel<<<(n * 256 + 255) / 256, 256>>>(p_x, n * 256, p_xhi, p_xlo);
        gemm_mma_kernel<<<dim3(n / 128, 2), 256, MMA_SMEM>>>(p_xhi, p_xlo, p_whi, p_wlo, p_h, 256);
        csr_build_kernel<<<G, 256>>>(p_es1, p_ed1, p_ew1, npg,
                                     p_rs, p_rc, p_cpack, p_dinv);
        agg_fused_kernel<<<dim3(4, G), 256, npg*64*4>>>(p_h, p_dinv, p_rs, p_rc,
                                                        p_cpack, gcn_b2, p_agg, npg);
    }
    {
        int npg = 64, k = 32;
        wnorm_kernel<<<1, 256>>>(pool_w2);
        score_kernel<<<(n * 32 + 255) / 256, 256>>>(p_agg, pool_w2, p_score, n);
        pool_kernel<<<G, npg>>>(p_score, npg, k, p_newid, p_perm);
        gather_scale_kernel<<<(G * k * HF + 255) / 256, 256>>>(p_agg, p_score, p_perm, p_x, G * k);
        readout_kernel<<<G, 256>>>(p_x, k, p_ro, 1);
    }

    // ---------------- MLP head ----------------
    lin1_kernel<<<32, 256>>>(p_ro, lin1_w, lin1_b, p_h1);
    lin2_kernel<<<16, 128>>>(p_h1, lin2_w, lin2_b, p_h2);
    lin3_lsm_kernel<<<G, 32>>>(p_h2, lin3_w, lin3_b, out);
}